// round 4
// baseline (speedup 1.0000x reference)
#include <cuda_runtime.h>
#include <math.h>

#define NN 100000
#define EE 1600000
#define HDIM 64

// ---------------- scratch (static device arrays; no allocation) -------------
__device__ float g_q[NN * HDIM];
__device__ float g_k[NN * HDIM];
__device__ float g_v[NN * HDIM];
__device__ float g_s[NN * HDIM];
__device__ int   g_off[NN + 1];

// ---------------- packed f32x2 helpers (sm_100+ FFMA2) ----------------------
typedef unsigned long long u64;

__device__ __forceinline__ u64 dup_f32x2(float x) {
    u64 d;
    asm("mov.b64 %0, {%1, %1};" : "=l"(d) : "f"(x));
    return d;
}
__device__ __forceinline__ void fma_f32x2(u64& d, u64 a, u64 b) {
    asm("fma.rn.f32x2 %0, %1, %2, %3;" : "=l"(d) : "l"(a), "l"(b), "l"(d));
}
__device__ __forceinline__ float2 unpack_f32x2(u64 d) {
    float2 f;
    asm("mov.b64 {%0, %1}, %2;" : "=f"(f.x), "=f"(f.y) : "l"(d));
    return f;
}

// ---------------- K1: fused projection GEMM  [N,64] @ [64,256] --------------
// cols 0-63 -> q, 64-127 -> k, 128-191 -> v, 192-255 -> skip
// 8 rows x 4 f32x2-col-pairs per thread, packed FFMA2 inner loop.
__global__ void __launch_bounds__(256, 2)
proj_kernel(const float* __restrict__ feat,
            const float* __restrict__ Wq, const float* __restrict__ bq,
            const float* __restrict__ Wk, const float* __restrict__ bk,
            const float* __restrict__ Wv, const float* __restrict__ bv,
            const float* __restrict__ Ws, const float* __restrict__ bs)
{
    extern __shared__ float sm[];
    float* Wsm = sm;                 // 64*256
    float* fT  = sm + 64 * 256;      // 64*68 (transposed, padded)
    float* bsm = fT + 64 * 68;       // 256

    const int tid = threadIdx.x;

    for (int i = tid; i < 64 * 256; i += 256) {
        int kk = i >> 8, c = i & 255;
        int m = c >> 6, lc = c & 63;
        const float* W = (m == 0) ? Wq : (m == 1) ? Wk : (m == 2) ? Wv : Ws;
        Wsm[kk * 256 + c] = W[kk * 64 + lc];
    }
    {
        int c = tid, m = c >> 6, lc = c & 63;
        const float* b = (m == 0) ? bq : (m == 1) ? bk : (m == 2) ? bv : bs;
        bsm[c] = b[lc];
    }

    const int r0 = (tid >> 5) * 8;   // 0..56
    const int c0 = (tid & 31) * 8;   // 0..248
    const int mm = c0 >> 6, lc = c0 & 63;
    float* obase = (mm == 0) ? g_q : (mm == 1) ? g_k : (mm == 2) ? g_v : g_s;

    const int numTiles = (NN + 63) / 64;
    for (int tile = blockIdx.x; tile < numTiles; tile += gridDim.x) {
        const int rowbase = tile * 64;
        __syncthreads();
        for (int i = tid; i < 64 * 16; i += 256) {
            int r = i >> 4;
            int c4 = (i & 15) * 4;
            int row = rowbase + r;
            float4 vv = (row < NN) ? *(const float4*)&feat[row * 64 + c4]
                                   : make_float4(0.f, 0.f, 0.f, 0.f);
            fT[(c4 + 0) * 68 + r] = vv.x;
            fT[(c4 + 1) * 68 + r] = vv.y;
            fT[(c4 + 2) * 68 + r] = vv.z;
            fT[(c4 + 3) * 68 + r] = vv.w;
        }
        __syncthreads();

        // acc2[i][j] holds cols (c0+2j, c0+2j+1) for row r0+i
        u64 acc2[32];
#pragma unroll
        for (int i = 0; i < 32; i++) acc2[i] = 0ull;

#pragma unroll 4
        for (int kk = 0; kk < 64; kk++) {
            const float4 fa = *(const float4*)(fT + kk * 68 + r0);
            const float4 fb = *(const float4*)(fT + kk * 68 + r0 + 4);
            // weight pairs load naturally packed from smem
            const u64* wp = (const u64*)(Wsm + kk * 256 + c0);
            const u64 w0 = wp[0], w1 = wp[1], w2 = wp[2], w3 = wp[3];
            const float f[8] = {fa.x, fa.y, fa.z, fa.w, fb.x, fb.y, fb.z, fb.w};
#pragma unroll
            for (int i = 0; i < 8; i++) {
                const u64 fd = dup_f32x2(f[i]);
                fma_f32x2(acc2[i * 4 + 0], fd, w0);
                fma_f32x2(acc2[i * 4 + 1], fd, w1);
                fma_f32x2(acc2[i * 4 + 2], fd, w2);
                fma_f32x2(acc2[i * 4 + 3], fd, w3);
            }
        }

#pragma unroll
        for (int i = 0; i < 8; i++) {
            int row = rowbase + r0 + i;
            if (row < NN) {
                float2 p0 = unpack_f32x2(acc2[i * 4 + 0]);
                float2 p1 = unpack_f32x2(acc2[i * 4 + 1]);
                float2 p2 = unpack_f32x2(acc2[i * 4 + 2]);
                float2 p3 = unpack_f32x2(acc2[i * 4 + 3]);
                float4 o;
                o.x = p0.x + bsm[c0 + 0];
                o.y = p0.y + bsm[c0 + 1];
                o.z = p1.x + bsm[c0 + 2];
                o.w = p1.y + bsm[c0 + 3];
                *(float4*)&obase[row * 64 + lc] = o;
                o.x = p2.x + bsm[c0 + 4];
                o.y = p2.y + bsm[c0 + 5];
                o.z = p3.x + bsm[c0 + 6];
                o.w = p3.y + bsm[c0 + 7];
                *(float4*)&obase[row * 64 + lc + 4] = o;
            }
        }
    }
}

// ---------------- K2: CSR offsets via binary search on sorted edge_dst ------
__global__ void offsets_kernel(const int* __restrict__ dst)
{
    int n = blockIdx.x * blockDim.x + threadIdx.x;
    if (n > NN) return;
    if (n == NN) { g_off[NN] = EE; return; }
    int lo = 0, hi = EE;
    while (lo < hi) {
        int mid = (lo + hi) >> 1;
        if (dst[mid] < n) lo = mid + 1; else hi = mid;
    }
    g_off[n] = lo;
}

// ---------------- K3: fused edge attention + gate + LN + PReLU --------------
// one warp per destination node; lane l owns elements 2l, 2l+1 (head = l/8)
// 4 edges per iteration for MLP=4 on the gather loads.
__global__ void attn_kernel(const int* __restrict__ src_idx,
                            const float* __restrict__ Wg, const float* __restrict__ bg,
                            const float* __restrict__ ln_g, const float* __restrict__ ln_b,
                            const float* __restrict__ prelu_a,
                            float* __restrict__ out)
{
    const int warp = (blockIdx.x * blockDim.x + threadIdx.x) >> 5;
    const int lane = threadIdx.x & 31;
    if (warp >= NN) return;
    const int n = warp;
    const int e0 = lane * 2;

    const float2 kd = *(const float2*)&g_k[n * HDIM + e0];
    const int start = g_off[n];
    const int end   = g_off[n + 1];

    float m = -1e30f, s = 0.f, a0 = 0.f, a1 = 0.f;

    int e = start;
    for (; e + 4 <= end; e += 4) {
        const int s0i = __ldg(&src_idx[e]);
        const int s1i = __ldg(&src_idx[e + 1]);
        const int s2i = __ldg(&src_idx[e + 2]);
        const int s3i = __ldg(&src_idx[e + 3]);
        const float2 q0 = *(const float2*)&g_q[s0i * HDIM + e0];
        const float2 q1 = *(const float2*)&g_q[s1i * HDIM + e0];
        const float2 q2 = *(const float2*)&g_q[s2i * HDIM + e0];
        const float2 q3 = *(const float2*)&g_q[s3i * HDIM + e0];
        const float2 v0 = *(const float2*)&g_v[s0i * HDIM + e0];
        const float2 v1 = *(const float2*)&g_v[s1i * HDIM + e0];
        const float2 v2 = *(const float2*)&g_v[s2i * HDIM + e0];
        const float2 v3 = *(const float2*)&g_v[s3i * HDIM + e0];

        float p0 = q0.x * kd.x + q0.y * kd.y;
        float p1 = q1.x * kd.x + q1.y * kd.y;
        float p2 = q2.x * kd.x + q2.y * kd.y;
        float p3 = q3.x * kd.x + q3.y * kd.y;
#pragma unroll
        for (int d = 1; d <= 4; d <<= 1) {
            p0 += __shfl_xor_sync(0xffffffffu, p0, d);
            p1 += __shfl_xor_sync(0xffffffffu, p1, d);
            p2 += __shfl_xor_sync(0xffffffffu, p2, d);
            p3 += __shfl_xor_sync(0xffffffffu, p3, d);
        }
        const float sc0 = p0 * 0.25f;   // 1/sqrt(16)
        const float sc1 = p1 * 0.25f;
        const float sc2 = p2 * 0.25f;
        const float sc3 = p3 * 0.25f;

        const float nm = fmaxf(fmaxf(m, fmaxf(sc0, sc1)), fmaxf(sc2, sc3));
        const float rs = __expf(m - nm);
        const float e0x = __expf(sc0 - nm);
        const float e1x = __expf(sc1 - nm);
        const float e2x = __expf(sc2 - nm);
        const float e3x = __expf(sc3 - nm);
        s  = s  * rs + e0x + e1x + e2x + e3x;
        a0 = a0 * rs + e0x * v0.x + e1x * v1.x + e2x * v2.x + e3x * v3.x;
        a1 = a1 * rs + e0x * v0.y + e1x * v1.y + e2x * v2.y + e3x * v3.y;
        m = nm;
    }
    for (; e < end; e++) {
        const int src = __ldg(&src_idx[e]);
        const float2 qs = *(const float2*)&g_q[src * HDIM + e0];
        const float2 vs = *(const float2*)&g_v[src * HDIM + e0];
        float p = qs.x * kd.x + qs.y * kd.y;
        p += __shfl_xor_sync(0xffffffffu, p, 1);
        p += __shfl_xor_sync(0xffffffffu, p, 2);
        p += __shfl_xor_sync(0xffffffffu, p, 4);
        const float score = p * 0.25f;
        const float nm = fmaxf(m, score);
        const float rs = __expf(m - nm);
        const float pe = __expf(score - nm);
        s  = s  * rs + pe;
        a0 = a0 * rs + pe * vs.x;
        a1 = a1 * rs + pe * vs.y;
        m = nm;
    }

    if (end > start) {
        const float inv = 1.f / s;
        a0 *= inv; a1 *= inv;
    } else {
        a0 = 0.f; a1 = 0.f;
    }

    // gated skip: gate = sigmoid([skip, rst, skip-rst] @ Wg + bg)
    const float2 sk = *(const float2*)&g_s[n * HDIM + e0];
    float gd = sk.x * Wg[e0] + sk.y * Wg[e0 + 1]
             + a0 * Wg[64 + e0] + a1 * Wg[64 + e0 + 1]
             + (sk.x - a0) * Wg[128 + e0] + (sk.y - a1) * Wg[128 + e0 + 1];
#pragma unroll
    for (int d = 1; d <= 16; d <<= 1)
        gd += __shfl_xor_sync(0xffffffffu, gd, d);
    const float gate = 1.f / (1.f + __expf(-(gd + bg[0])));

    float r0v = gate * sk.x + (1.f - gate) * a0;
    float r1v = gate * sk.y + (1.f - gate) * a1;

    // layer norm over 64
    float msum = r0v + r1v;
#pragma unroll
    for (int d = 1; d <= 16; d <<= 1)
        msum += __shfl_xor_sync(0xffffffffu, msum, d);
    const float mu = msum * (1.f / 64.f);
    const float dx = r0v - mu, dy = r1v - mu;
    float vsum = dx * dx + dy * dy;
#pragma unroll
    for (int d = 1; d <= 16; d <<= 1)
        vsum += __shfl_xor_sync(0xffffffffu, vsum, d);
    const float var = vsum * (1.f / 64.f);
    const float rstd = rsqrtf(var + 1e-5f);

    float y0 = dx * rstd * ln_g[e0]     + ln_b[e0];
    float y1 = dy * rstd * ln_g[e0 + 1] + ln_b[e0 + 1];

    const float alpha = prelu_a[0];
    y0 = (y0 >= 0.f) ? y0 : alpha * y0;
    y1 = (y1 >= 0.f) ? y1 : alpha * y1;

    float2 o; o.x = y0; o.y = y1;
    *(float2*)&out[n * HDIM + e0] = o;
}

// ---------------- launch -----------------------------------------------------
extern "C" void kernel_launch(void* const* d_in, const int* in_sizes, int n_in,
                              void* d_out, int out_size)
{
    const float* feat   = (const float*)d_in[0];
    const int*   esrc   = (const int*)d_in[1];
    const int*   edst   = (const int*)d_in[2];
    const float* Wq     = (const float*)d_in[3];
    const float* bq     = (const float*)d_in[4];
    const float* Wk     = (const float*)d_in[5];
    const float* bk     = (const float*)d_in[6];
    const float* Wv     = (const float*)d_in[7];
    const float* bv     = (const float*)d_in[8];
    const float* Ws     = (const float*)d_in[9];
    const float* bs     = (const float*)d_in[10];
    const float* Wg     = (const float*)d_in[11];
    const float* bg     = (const float*)d_in[12];
    const float* ln_g   = (const float*)d_in[13];
    const float* ln_b   = (const float*)d_in[14];
    const float* pa     = (const float*)d_in[15];
    float* out = (float*)d_out;

    const int smem = (64 * 256 + 64 * 68 + 256) * sizeof(float); // 83968 B
    cudaFuncSetAttribute(proj_kernel, cudaFuncAttributeMaxDynamicSharedMemorySize, smem);

    proj_kernel<<<296, 256, smem>>>(feat, Wq, bq, Wk, bk, Wv, bv, Ws, bs);
    offsets_kernel<<<(NN + 1 + 255) / 256, 256>>>(edst);
    attn_kernel<<<(NN + 7) / 8, 256>>>(esrc, Wg, bg, ln_g, ln_b, pa, out);
}